// round 13
// baseline (speedup 1.0000x reference)
#include <cuda_runtime.h>
#include <cuda_bf16.h>

#define EPS_CLAMP 1e-4f
#define BLK 128

__device__ float g_M[27];   // M = W3 W2 W1, [9,3] row-major
__device__ float g_C9[81];  // EPS * (I - M M^T)

// ---------------------------------------------------------------------------
// Prep kernel: M = W3 (W2 W1), C9 = EPS*(I - M M^T). One small block.
// ---------------------------------------------------------------------------
__global__ void spd_prep_kernel(const float* __restrict__ W1,
                                const float* __restrict__ W2,
                                const float* __restrict__ W3) {
    __shared__ float W21[21];  // [7,3]
    __shared__ float sM[27];
    int t = threadIdx.x;  // 96 threads

    if (t < 21) {
        int i = t / 3, k = t % 3;
        float s = 0.f;
        #pragma unroll
        for (int a = 0; a < 5; a++) s += W2[i*5+a] * W1[a*3+k];
        W21[t] = s;
    }
    __syncthreads();
    if (t < 27) {
        int r = t / 3, k = t % 3;
        float s = 0.f;
        #pragma unroll
        for (int a = 0; a < 7; a++) s += W3[r*7+a] * W21[a*3+k];
        sM[t] = s;
        g_M[t] = s;
    }
    __syncthreads();
    if (t < 81) {
        int i = t / 9, j = t % 9;
        float d = sM[i*3+0]*sM[j*3+0] + sM[i*3+1]*sM[j*3+1] + sM[i*3+2]*sM[j*3+2];
        g_C9[t] = EPS_CLAMP * ((i == j ? 1.0f : 0.0f) - d);
    }
}

// Symmetric 3x3 packed as [00,01,02,11,12,22]; u = a*b for commuting a,b.
__device__ __forceinline__ void symprod(const float a[6], const float b[6],
                                        float u[6]) {
    u[0] = a[0]*b[0] + a[1]*b[1] + a[2]*b[2];
    u[1] = a[0]*b[1] + a[1]*b[3] + a[2]*b[4];
    u[2] = a[0]*b[2] + a[1]*b[4] + a[2]*b[5];
    u[3] = a[1]*b[1] + a[3]*b[3] + a[4]*b[4];
    u[4] = a[1]*b[2] + a[3]*b[4] + a[4]*b[5];
    u[5] = a[2]*b[2] + a[4]*b[4] + a[5]*b[5];
}

// ---------------------------------------------------------------------------
// Main kernel: ZERO block barriers, zero MUFU. Warps fully autonomous from
// cycle 0. M / C9 via __ldg (uniform -> L1 broadcast after first warp).
// ---------------------------------------------------------------------------
__global__ void __launch_bounds__(BLK)
spd_main_kernel(const float* __restrict__ vech, float* __restrict__ out, int B) {
    __shared__ __align__(16) float stage[BLK * 81];  // 4 warp slices

    const int t    = threadIdx.x;
    const int w    = t >> 5;
    const int lane = t & 31;
    const int item0 = blockIdx.x * BLK;
    const int nItems = min(BLK, B - item0);

    // ---- warp-local vech staging (starts immediately, no prologue) ----
    const int wItem0 = item0 + w * 32;
    const int wn = max(0, min(32, nItems - w * 32));
    float* const slice = &stage[w * 32 * 81];

    if (wn == 32) {
        #pragma unroll
        for (int k = 0; k < 6; k++)
            slice[k * 32 + lane] = vech[(size_t)wItem0 * 6 + k * 32 + lane];
    } else {
        for (int idx = lane; idx < wn * 6; idx += 32)
            slice[idx] = vech[(size_t)wItem0 * 6 + idx];
    }

    // M into registers while the STS above are in flight (uniform LDG)
    float M[27];
    #pragma unroll
    for (int i = 0; i < 27; i++) M[i] = __ldg(&g_M[i]);

    __syncwarp();
    float v[6];
    {   // float2 redistribute: 3 LDS.64
        const float2* s2 = reinterpret_cast<const float2*>(slice);
        float2 p0 = s2[lane * 3 + 0];
        float2 p1 = s2[lane * 3 + 1];
        float2 p2 = s2[lane * 3 + 2];
        v[0] = p0.x; v[1] = p0.y; v[2] = p1.x;
        v[3] = p1.y; v[4] = p2.x; v[5] = p2.y;
    }
    __syncwarp();

    const bool active = lane < wn;
    if (active) {
        // ---- S = A / 64 ----
        float S[6];
        #pragma unroll
        for (int i = 0; i < 6; i++) S[i] = v[i] * 0.015625f;

        // ---- T = Taylor7(S), matrix Horner ----
        float T[6], U[6];
        #pragma unroll
        for (int i = 0; i < 6; i++) T[i] = S[i] * (1.0f / 7.0f);
        T[0] += 1.0f; T[3] += 1.0f; T[5] += 1.0f;
        #pragma unroll
        for (int k = 6; k >= 1; k--) {
            symprod(S, T, U);
            const float rk = (k == 6) ? (1.0f/6.0f) :
                             (k == 5) ? (1.0f/5.0f) :
                             (k == 4) ? (1.0f/4.0f) :
                             (k == 3) ? (1.0f/3.0f) :
                             (k == 2) ? (1.0f/2.0f) : 1.0f;
            #pragma unroll
            for (int i = 0; i < 6; i++) T[i] = U[i] * rk;
            T[0] += 1.0f; T[3] += 1.0f; T[5] += 1.0f;
        }

        // ---- 6 squarings: X3 = T^(64) ----
        #pragma unroll
        for (int sq = 0; sq < 6; sq++) {
            symprod(T, T, U);
            #pragma unroll
            for (int i = 0; i < 6; i++) T[i] = U[i];
        }
        const float x00 = T[0], x01 = T[1], x02 = T[2];
        const float x11 = T[3], x12 = T[4], x22 = T[5];

        // ---- Y = M * X3   [9,3] ----
        float Y[9][3];
        #pragma unroll
        for (int rr = 0; rr < 9; rr++) {
            const float m0 = M[rr*3+0], m1 = M[rr*3+1], m2 = M[rr*3+2];
            Y[rr][0] = m0 * x00 + m1 * x01 + m2 * x02;
            Y[rr][1] = m0 * x01 + m1 * x11 + m2 * x12;
            Y[rr][2] = m0 * x02 + m1 * x12 + m2 * x22;
        }

        // ---- X9 = Y * M^T + C9 (symmetric) -> own slice ----
        float* st = &slice[lane * 81];
        #pragma unroll
        for (int rr = 0; rr < 9; rr++) {
            #pragma unroll
            for (int cc = rr; cc < 9; cc++) {
                const float val = Y[rr][0] * M[cc*3+0]
                                + Y[rr][1] * M[cc*3+1]
                                + Y[rr][2] * M[cc*3+2]
                                + __ldg(&g_C9[rr*9+cc]);
                st[rr*9+cc] = val;
                st[cc*9+rr] = val;
            }
        }
    }
    __syncwarp();

    // Coalesced copy of this warp's slice (2592 floats = 648 float4)
    if (wn == 32) {
        float4* o4 = reinterpret_cast<float4*>(out + (size_t)wItem0 * 81);
        const float4* s4 = reinterpret_cast<const float4*>(slice);
        #pragma unroll 7
        for (int idx = lane; idx < (32 * 81) / 4; idx += 32)
            o4[idx] = s4[idx];
    } else if (wn > 0) {
        float* ob = out + (size_t)wItem0 * 81;
        for (int idx = lane; idx < wn * 81; idx += 32)
            ob[idx] = slice[idx];
    }
}

// ---------------------------------------------------------------------------
extern "C" void kernel_launch(void* const* d_in, const int* in_sizes, int n_in,
                              void* d_out, int out_size) {
    const float* vech = nullptr;
    const float* W1 = nullptr;
    const float* W2 = nullptr;
    const float* W3 = nullptr;
    int vech_elems = 0;
    for (int i = 0; i < n_in; i++) {
        int sz = in_sizes[i];
        if (sz == 15)      W1 = (const float*)d_in[i];
        else if (sz == 35) W2 = (const float*)d_in[i];
        else if (sz == 63) W3 = (const float*)d_in[i];
        else { vech = (const float*)d_in[i]; vech_elems = sz; }
    }
    int B = vech_elems / 6;
    spd_prep_kernel<<<1, 96>>>(W1, W2, W3);
    int grid = (B + BLK - 1) / BLK;
    spd_main_kernel<<<grid, BLK>>>(vech, (float*)d_out, B);
}

// round 15
// speedup vs baseline: 1.1925x; 1.1925x over previous
#include <cuda_runtime.h>
#include <cuda_bf16.h>

#define EPS_CLAMP 1e-4f
#define BLK 128
#define WPB (BLK / 32)
#define MAXBLOCKS 740   // 148 SMs x 5 resident (smem-capped) = one wave

// Symmetric 3x3 packed [00,01,02,11,12,22]; u = a*b for commuting symmetric.
__device__ __forceinline__ void symprod(const float a[6], const float b[6],
                                        float u[6]) {
    u[0] = a[0]*b[0] + a[1]*b[1] + a[2]*b[2];
    u[1] = a[0]*b[1] + a[1]*b[3] + a[2]*b[4];
    u[2] = a[0]*b[2] + a[1]*b[4] + a[2]*b[5];
    u[3] = a[1]*b[1] + a[3]*b[3] + a[4]*b[4];
    u[4] = a[1]*b[2] + a[3]*b[4] + a[4]*b[5];
    u[5] = a[2]*b[2] + a[4]*b[4] + a[5]*b[5];
}

// ---------------------------------------------------------------------------
// Single-launch, persistent, warp-autonomous SPDNet decoder.
//  - Each warp loops over 32-item tiles (grid-stride), prefetching the next
//    tile's vech into registers while computing the current tile.
//  - M = W3 W2 W1 computed per-warp once (uniform; hidden under first LDG).
//  - X9 = M (X3 - EPS I) M^T + EPS I   (C9 identity: telescoped + folded).
//  - exp(A) = Taylor7(A/64)^(64), zero MUFU, branch-free.
//  - ZERO block barriers; smem transpose + coalesced float4 stores.
// ---------------------------------------------------------------------------
__global__ void __launch_bounds__(BLK)
spd_main_kernel(const float* __restrict__ vech,
                const float* __restrict__ W1,
                const float* __restrict__ W2,
                const float* __restrict__ W3,
                float* __restrict__ out, int B) {
    __shared__ __align__(16) float stage[WPB][32 * 81];  // 41472 B

    const int w    = threadIdx.x >> 5;
    const int lane = threadIdx.x & 31;
    const int nTiles = (B + 31) >> 5;
    const int warpStride = gridDim.x * WPB;
    int tile = blockIdx.x * WPB + w;

    float* const slice = stage[w];

    // ---- fire first prefetch ASAP (before anything else) ----
    float pf[6];
    bool pfFull = false;
    if (tile < nTiles) {
        const int i0 = tile << 5;
        pfFull = (B - i0 >= 32);
        if (pfFull) {
            #pragma unroll
            for (int k = 0; k < 6; k++)
                pf[k] = vech[(size_t)i0 * 6 + k * 32 + lane];
        }
    }

    // ---- per-warp M = W3 (W2 W1): uniform, overlaps prefetch latency ----
    float M[27];
    {
        float w21[21];
        #pragma unroll
        for (int a = 0; a < 7; a++) {
            #pragma unroll
            for (int k = 0; k < 3; k++) {
                float s = 0.f;
                #pragma unroll
                for (int b = 0; b < 5; b++) s += W2[a*5+b] * W1[b*3+k];
                w21[a*3+k] = s;
            }
        }
        #pragma unroll
        for (int r = 0; r < 9; r++) {
            #pragma unroll
            for (int k = 0; k < 3; k++) {
                float s = 0.f;
                #pragma unroll
                for (int a = 0; a < 7; a++) s += W3[r*7+a] * w21[a*3+k];
                M[r*3+k] = s;
            }
        }
    }

    // ---- persistent tile loop ----
    while (tile < nTiles) {
        const int wItem0 = tile << 5;
        const int wn = min(32, B - wItem0);
        const int nextTile = tile + warpStride;

        // stage current tile's vech into slice
        if (pfFull) {
            #pragma unroll
            for (int k = 0; k < 6; k++)
                slice[k * 32 + lane] = pf[k];
        } else {
            for (int idx = lane; idx < wn * 6; idx += 32)
                slice[idx] = vech[(size_t)wItem0 * 6 + idx];
        }
        __syncwarp();

        float v[6];
        {   // float2 redistribute: 3 LDS.64
            const float2* s2 = reinterpret_cast<const float2*>(slice);
            float2 p0 = s2[lane * 3 + 0];
            float2 p1 = s2[lane * 3 + 1];
            float2 p2 = s2[lane * 3 + 2];
            v[0] = p0.x; v[1] = p0.y; v[2] = p1.x;
            v[3] = p1.y; v[4] = p2.x; v[5] = p2.y;
        }
        __syncwarp();  // slice reads done; free for output staging

        // prefetch NEXT tile (latency hides under math + stores below)
        pfFull = false;
        if (nextTile < nTiles) {
            const int ni0 = nextTile << 5;
            pfFull = (B - ni0 >= 32);
            if (pfFull) {
                #pragma unroll
                for (int k = 0; k < 6; k++)
                    pf[k] = vech[(size_t)ni0 * 6 + k * 32 + lane];
            }
        }

        if (lane < wn) {
            // ---- S = A / 64 ----
            float S[6];
            #pragma unroll
            for (int i = 0; i < 6; i++) S[i] = v[i] * 0.015625f;

            // ---- T = Taylor7(S), matrix Horner ----
            float T[6], U[6];
            #pragma unroll
            for (int i = 0; i < 6; i++) T[i] = S[i] * (1.0f / 7.0f);
            T[0] += 1.0f; T[3] += 1.0f; T[5] += 1.0f;
            #pragma unroll
            for (int k = 6; k >= 1; k--) {
                symprod(S, T, U);
                const float rk = (k == 6) ? (1.0f/6.0f) :
                                 (k == 5) ? (1.0f/5.0f) :
                                 (k == 4) ? (1.0f/4.0f) :
                                 (k == 3) ? (1.0f/3.0f) :
                                 (k == 2) ? (1.0f/2.0f) : 1.0f;
                #pragma unroll
                for (int i = 0; i < 6; i++) T[i] = U[i] * rk;
                T[0] += 1.0f; T[3] += 1.0f; T[5] += 1.0f;
            }

            // ---- 6 squarings: X3 = T^(64) ----
            #pragma unroll
            for (int sq = 0; sq < 6; sq++) {
                symprod(T, T, U);
                #pragma unroll
                for (int i = 0; i < 6; i++) T[i] = U[i];
            }

            // ---- X' = X3 - EPS*I (folds ReEig constant) ----
            T[0] -= EPS_CLAMP; T[3] -= EPS_CLAMP; T[5] -= EPS_CLAMP;
            const float x00 = T[0], x01 = T[1], x02 = T[2];
            const float x11 = T[3], x12 = T[4], x22 = T[5];

            // ---- X9 = M X' M^T + EPS*I, row-fused (3 live Y regs) ----
            float* st = &slice[lane * 81];
            #pragma unroll
            for (int rr = 0; rr < 9; rr++) {
                const float m0 = M[rr*3+0], m1 = M[rr*3+1], m2 = M[rr*3+2];
                const float y0 = m0 * x00 + m1 * x01 + m2 * x02;
                const float y1 = m0 * x01 + m1 * x11 + m2 * x12;
                const float y2 = m0 * x02 + m1 * x12 + m2 * x22;
                #pragma unroll
                for (int cc = rr; cc < 9; cc++) {
                    float val = y0 * M[cc*3+0] + y1 * M[cc*3+1] + y2 * M[cc*3+2];
                    if (cc == rr) val += EPS_CLAMP;
                    st[rr*9+cc] = val;
                    st[cc*9+rr] = val;
                }
            }
        }
        __syncwarp();

        // ---- coalesced copy slice -> gmem ----
        if (wn == 32) {
            float4* o4 = reinterpret_cast<float4*>(out + (size_t)wItem0 * 81);
            const float4* s4 = reinterpret_cast<const float4*>(slice);
            #pragma unroll 7
            for (int idx = lane; idx < (32 * 81) / 4; idx += 32)
                o4[idx] = s4[idx];
        } else if (wn > 0) {
            float* ob = out + (size_t)wItem0 * 81;
            for (int idx = lane; idx < wn * 81; idx += 32)
                ob[idx] = slice[idx];
        }

        tile = nextTile;
        __syncwarp();  // copy LDS ordered before next stage STS (WAR)
    }
}

// ---------------------------------------------------------------------------
extern "C" void kernel_launch(void* const* d_in, const int* in_sizes, int n_in,
                              void* d_out, int out_size) {
    const float* vech = nullptr;
    const float* W1 = nullptr;
    const float* W2 = nullptr;
    const float* W3 = nullptr;
    int vech_elems = 0;
    for (int i = 0; i < n_in; i++) {
        int sz = in_sizes[i];
        if (sz == 15)      W1 = (const float*)d_in[i];
        else if (sz == 35) W2 = (const float*)d_in[i];
        else if (sz == 63) W3 = (const float*)d_in[i];
        else { vech = (const float*)d_in[i]; vech_elems = sz; }
    }
    int B = vech_elems / 6;
    int nTiles = (B + 31) / 32;
    int grid = (nTiles + WPB - 1) / WPB;
    if (grid > MAXBLOCKS) grid = MAXBLOCKS;
    spd_main_kernel<<<grid, BLK>>>(vech, W1, W2, W3, (float*)d_out, B);
}